// round 17
// baseline (speedup 1.0000x reference)
#include <cuda_runtime.h>
#include <cuda_fp16.h>
#include <math.h>
#include <stdint.h>

// Problem constants
#define BB 2
#define LL 4096
#define DD 1024
#define HH 16
#define GG 2
#define HD 64
#define KVD 128
#define KVC 256
#define QKVC 1280        // Q(1024) | K(128) | V(128)
#define EE 8
#define HID 1024
#define NTOK (BB*LL)     // 8192
#define NWIN 16
#define WIN 256
#define TCK 32           // K-chunk (32 fp16 columns per stage)
#define NCH (DD/TCK)     // 32 chunks
#define BSTR 40          // padded smem row stride (80B, ldmatrix conflict-free)
#define TILE (128*BSTR)
#define TILEB (TILE*2)   // 10240 bytes
#define BUFB (2*TILEB)   // one stage = A|B = 20480 bytes
#define NSTAGE 3
#define GSMEM (NSTAGE*BUFB)  // 61440 -> 3 CTAs/SM (with regs <= 85)
#define APAD 72          // attention smem row stride

// ---------------- scratch (static device globals) ----------------
__device__ __align__(16) __half g_ln1 [NTOK*DD];
__device__ __align__(16) __half g_qh  [NTOK*DD];      // Q, pre-scaled 1/8, fp16
__device__ __align__(16) __half g_kh  [NTOK*KVD];     // K fp16 [token][128]
__device__ __align__(16) __half g_vt  [BB*GG*64*LL];  // V fp16 transposed [(b,g,dim)][pos]
__device__ __align__(16) __half g_att [NTOK*DD];
__device__ __align__(16) __half g_ln2 [NTOK*DD];
__device__ __align__(16) __half g_wqkv[QKVC*DD];
__device__ __align__(16) __half g_wot [DD*DD];
__device__ __align__(16) __half g_wet [EE*DD*HID];
__device__ float g_bqkv[QKVC];
__device__ int   g_ecount[EE];
__device__ float g_entsum;
__device__ int   g_etok[EE*NTOK];   // tok*2 + slot
__device__ float g_ewt [EE*NTOK];

// ---------------- helpers ----------------
__device__ __forceinline__ uint32_t su32(const void* p) {
    uint32_t r;
    asm("{ .reg .u64 t; cvta.to.shared.u64 t, %1; cvt.u32.u64 %0, t; }" : "=r"(r) : "l"(p));
    return r;
}
#define CP16(dst, src) asm volatile("cp.async.cg.shared.global [%0], [%1], 16;" :: "r"(dst), "l"(src))
#define CP_COMMIT()    asm volatile("cp.async.commit_group;" ::: "memory")
#define CP_WAIT0()     asm volatile("cp.async.wait_group 0;" ::: "memory")
#define CP_WAIT1()     asm volatile("cp.async.wait_group 1;" ::: "memory")

#define LDSM4(r0, r1, r2, r3, addr) \
    asm volatile("ldmatrix.sync.aligned.m8n8.x4.shared.b16 {%0,%1,%2,%3}, [%4];" \
                 : "=r"(r0), "=r"(r1), "=r"(r2), "=r"(r3) : "r"(addr))

__device__ __forceinline__ void mma_f16(float* c, const uint32_t* a, const uint32_t* b) {
    asm volatile(
        "mma.sync.aligned.m16n8k16.row.col.f32.f16.f16.f32 "
        "{%0,%1,%2,%3}, {%4,%5,%6,%7}, {%8,%9}, {%0,%1,%2,%3};"
        : "+f"(c[0]), "+f"(c[1]), "+f"(c[2]), "+f"(c[3])
        : "r"(a[0]), "r"(a[1]), "r"(a[2]), "r"(a[3]), "r"(b[0]), "r"(b[1]));
}
// single-instruction fp32x2 -> fp16x2 pack
__device__ __forceinline__ uint32_t packf2(float lo, float hi) {
    __half2 h = __floats2half2_rn(lo, hi);
    return *(uint32_t*)&h;
}

// ---------------- weight prep part A: Wq|Wk|Wv + bias + zero ---------------
__global__ void __launch_bounds__(256)
transpose_qkv(const float* __restrict__ Wq, const float* __restrict__ Wk,
              const float* __restrict__ Wv,
              const float* __restrict__ bq, const float* __restrict__ bk,
              const float* __restrict__ bv) {
    __shared__ float t[32][33];
    int bid = blockIdx.x;
    if (bid >= 1280) {
        int tt = threadIdx.y * 32 + threadIdx.x + (bid - 1280) * 256;
        if (tt < DD) g_bqkv[tt] = bq[tt];
        else if (tt < DD + KVD) g_bqkv[tt] = bk[tt - DD];
        else if (tt < QKVC) g_bqkv[tt] = bv[tt - DD - KVD];
        if (bid == 1280) {
            if (tt < EE) g_ecount[tt] = 0;
            if (tt == EE) g_entsum = 0.f;
        }
        return;
    }
    const float* src;
    int cols, rowOff, bx, by;
    if (bid < 1024) {
        src = Wq; cols = DD; rowOff = 0;
        bx = bid & 31; by = bid >> 5;
    } else if (bid < 1152) {
        int r = bid - 1024;
        src = Wk; cols = KVD; rowOff = DD;
        bx = r & 3; by = r >> 2;
    } else {
        int r = bid - 1152;
        src = Wv; cols = KVD; rowOff = DD + KVD;
        bx = r & 3; by = r >> 2;
    }
    int c0 = bx * 32, r0 = by * 32;
    int tx = threadIdx.x, ty = threadIdx.y;
    #pragma unroll
    for (int i = 0; i < 32; i += 8)
        t[ty + i][tx] = src[(size_t)(r0 + ty + i) * cols + c0 + tx];
    __syncthreads();
    #pragma unroll
    for (int i = 0; i < 32; i += 8) {
        size_t o = (size_t)(c0 + ty + i + rowOff) * DD + r0 + tx;
        g_wqkv[o] = __float2half_rn(t[tx][ty + i]);
    }
}

// ---------------- weight prep part B: Wo + We (side stream) ----------------
__global__ void __launch_bounds__(256)
transpose_owe(const float* __restrict__ Wo, const float* __restrict__ We) {
    __shared__ float t[32][33];
    int bid = blockIdx.x;
    const float* src;
    __half* dh;
    int cols, bx, by;
    size_t dstOff = 0;
    if (bid < 1024) {
        src = Wo; dh = g_wot; cols = DD;
        bx = bid & 31; by = bid >> 5;
    } else {
        int r = bid - 1024;
        int e = r >> 10; r &= 1023;
        src = We + (size_t)e * DD * HID;
        dh = g_wet; dstOff = (size_t)e * DD * HID;
        cols = HID;
        bx = r & 31; by = r >> 5;
    }
    int c0 = bx * 32, r0 = by * 32;
    int tx = threadIdx.x, ty = threadIdx.y;
    #pragma unroll
    for (int i = 0; i < 32; i += 8)
        t[ty + i][tx] = src[(size_t)(r0 + ty + i) * cols + c0 + tx];
    __syncthreads();
    #pragma unroll
    for (int i = 0; i < 32; i += 8) {
        size_t o = dstOff + (size_t)(c0 + ty + i) * DD + r0 + tx;
        dh[o] = __float2half_rn(t[tx][ty + i]);
    }
}

// ---------------- LayerNorm (fp16 output) ----------
__global__ void ln_kernel(const float* __restrict__ x, const float* __restrict__ g,
                          const float* __restrict__ b, __half* __restrict__ y) {
    int row = blockIdx.x;
    const float4* xr = (const float4*)(x + (size_t)row * DD);
    int tid = threadIdx.x;
    float4 v = xr[tid];
    float s  = v.x + v.y + v.z + v.w;
    float ss = v.x*v.x + v.y*v.y + v.z*v.z + v.w*v.w;
    #pragma unroll
    for (int o = 16; o > 0; o >>= 1) {
        s  += __shfl_down_sync(0xffffffffu, s,  o);
        ss += __shfl_down_sync(0xffffffffu, ss, o);
    }
    __shared__ float sh_s[8], sh_ss[8];
    __shared__ float s_mean, s_rstd;
    int warp = tid >> 5, lane = tid & 31;
    if (lane == 0) { sh_s[warp] = s; sh_ss[warp] = ss; }
    __syncthreads();
    if (tid == 0) {
        float S = 0.f, SS = 0.f;
        #pragma unroll
        for (int i = 0; i < 8; i++) { S += sh_s[i]; SS += sh_ss[i]; }
        float mean = S / (float)DD;
        float var  = SS / (float)DD - mean * mean;
        s_mean = mean;
        s_rstd = rsqrtf(var + 1e-5f);
    }
    __syncthreads();
    float mean = s_mean, rstd = s_rstd;
    float4 gg = ((const float4*)g)[tid];
    float4 bb = ((const float4*)b)[tid];
    float o[4];
    o[0] = (v.x - mean) * rstd * gg.x + bb.x;
    o[1] = (v.y - mean) * rstd * gg.y + bb.y;
    o[2] = (v.z - mean) * rstd * gg.z + bb.z;
    o[3] = (v.w - mean) * rstd * gg.w + bb.w;
    size_t base = (size_t)row * DD + tid * 4;
    *(uint2*)&y[base] = make_uint2(packf2(o[0], o[1]), packf2(o[2], o[3]));
}

// ---------------- LN2 + MoE gate fused ----------------
__global__ void ln2_gate_kernel(const float* __restrict__ x, const float* __restrict__ g,
                                const float* __restrict__ b,
                                const float* __restrict__ Wg, const float* __restrict__ bg,
                                __half* __restrict__ y) {
    int row = blockIdx.x;
    const float4* xr = (const float4*)(x + (size_t)row * DD);
    int tid = threadIdx.x;
    float4 v = xr[tid];
    float s  = v.x + v.y + v.z + v.w;
    float ss = v.x*v.x + v.y*v.y + v.z*v.z + v.w*v.w;
    #pragma unroll
    for (int o = 16; o > 0; o >>= 1) {
        s  += __shfl_down_sync(0xffffffffu, s,  o);
        ss += __shfl_down_sync(0xffffffffu, ss, o);
    }
    __shared__ float sh_s[8], sh_ss[8];
    __shared__ float s_mean, s_rstd;
    __shared__ float red[8][8];
    int warp = tid >> 5, lane = tid & 31;
    if (lane == 0) { sh_s[warp] = s; sh_ss[warp] = ss; }
    __syncthreads();
    if (tid == 0) {
        float S = 0.f, SS = 0.f;
        #pragma unroll
        for (int i = 0; i < 8; i++) { S += sh_s[i]; SS += sh_ss[i]; }
        float mean = S / (float)DD;
        float var  = SS / (float)DD - mean * mean;
        s_mean = mean;
        s_rstd = rsqrtf(var + 1e-5f);
    }
    __syncthreads();
    float mean = s_mean, rstd = s_rstd;
    float4 gg = ((const float4*)g)[tid];
    float4 bb = ((const float4*)b)[tid];
    float o[4];
    o[0] = (v.x - mean) * rstd * gg.x + bb.x;
    o[1] = (v.y - mean) * rstd * gg.y + bb.y;
    o[2] = (v.z - mean) * rstd * gg.z + bb.z;
    o[3] = (v.w - mean) * rstd * gg.w + bb.w;
    size_t base = (size_t)row * DD + tid * 4;
    *(uint2*)&y[base] = make_uint2(packf2(o[0], o[1]), packf2(o[2], o[3]));

    // ---- gating from in-register LN output ----
    float pr[EE];
    #pragma unroll
    for (int e = 0; e < EE; e++) pr[e] = 0.f;
    #pragma unroll
    for (int i = 0; i < 4; i++) {
        float4 w0 = ((const float4*)Wg)[(tid * 4 + i) * 2];
        float4 w1 = ((const float4*)Wg)[(tid * 4 + i) * 2 + 1];
        pr[0] += o[i] * w0.x; pr[1] += o[i] * w0.y;
        pr[2] += o[i] * w0.z; pr[3] += o[i] * w0.w;
        pr[4] += o[i] * w1.x; pr[5] += o[i] * w1.y;
        pr[6] += o[i] * w1.z; pr[7] += o[i] * w1.w;
    }
    #pragma unroll
    for (int off = 16; off > 0; off >>= 1)
        #pragma unroll
        for (int e = 0; e < EE; e++)
            pr[e] += __shfl_down_sync(0xffffffffu, pr[e], off);
    if (lane == 0)
        #pragma unroll
        for (int e = 0; e < EE; e++) red[warp][e] = pr[e];
    __syncthreads();
    if (tid == 0) {
        float l[EE], m = -3.4e38f;
        #pragma unroll
        for (int e = 0; e < EE; e++) {
            float sum = bg[e];
            #pragma unroll
            for (int w = 0; w < 8; w++) sum += red[w][e];
            l[e] = sum;
            m = fmaxf(m, sum);
        }
        float p[EE], sm = 0.f;
        #pragma unroll
        for (int e = 0; e < EE; e++) { p[e] = __expf(l[e] - m); sm += p[e]; }
        float invs = 1.f / sm, ent = 0.f;
        #pragma unroll
        for (int e = 0; e < EE; e++) {
            p[e] *= invs;
            ent -= p[e] * logf(p[e] + 1e-8f);
        }
        atomicAdd(&g_entsum, ent);
        int i1 = 0;
        #pragma unroll
        for (int e = 1; e < EE; e++) if (p[e] > p[i1]) i1 = e;
        int i2 = (i1 == 0) ? 1 : 0;
        #pragma unroll
        for (int e = 0; e < EE; e++) if (e != i1 && p[e] > p[i2]) i2 = e;
        int s1 = atomicAdd(&g_ecount[i1], 1);
        g_etok[i1 * NTOK + s1] = row * 2 + 0; g_ewt[i1 * NTOK + s1] = p[i1];
        int s2 = atomicAdd(&g_ecount[i2], 1);
        g_etok[i2 * NTOK + s2] = row * 2 + 1; g_ewt[i2 * NTOK + s2] = p[i2];
    }
}

// ---------------- fp16 single-pass mma.sync GEMM (3-stage, 3 CTA/SM) ------
// MODE 1: QKV: cols<DD -> g_qh fp16 (scaled); K cols -> g_kh; V cols -> g_vt (transposed)
// MODE 2: C = acc + bias + resid
// MODE 3: MoE gathered rows; atomicAdd(C[tok*ldc+col], w*(acc+bias))
template<int MODE>
__global__ void __launch_bounds__(256, 3)
tc_gemm(const __half* __restrict__ A, const __half* __restrict__ B,
        const float* __restrict__ bias, const float* __restrict__ resid,
        float* __restrict__ C, int ldc) {
    __shared__ int   stok[128];
    __shared__ float swt[128];
    extern __shared__ __half smb[];

    int row0 = blockIdx.y * 128;
    int col0 = blockIdx.x * 128;
    int tid = threadIdx.x, wid = tid >> 5, lane = tid & 31;
    int quad = lane >> 2, tq = lane & 3;
    int wm = wid & 1, wn = wid >> 1;

    if (MODE == 3) {
        int e = blockIdx.z;
        int cnt = g_ecount[e];
        if (row0 >= cnt) return;
        B    += (size_t)e * DD * HID;
        bias += (size_t)e * HID;
        if (tid < 128) {
            int r = row0 + tid;
            if (r < cnt) { stok[tid] = g_etok[e * NTOK + r]; swt[tid] = g_ewt[e * NTOK + r]; }
            else         { stok[tid] = -1; swt[tid] = 0.f; }
        }
        __syncthreads();
    }

    int crow = tid >> 2;
    int seg  = tid & 3;
    // compact row indices (recompute pointers at prefetch to save regs)
    int arow[2], brow[2];
    uint32_t doff[2];
    #pragma unroll
    for (int i = 0; i < 2; i++) {
        int r = crow + 64 * i;
        int tok;
        if (MODE == 3) { int t2 = stok[r]; tok = (t2 < 0) ? 0 : (t2 >> 1); }
        else           tok = row0 + r;
        arow[i] = tok;
        brow[i] = col0 + r;
        doff[i] = (uint32_t)(r * (BSTR * 2) + seg * 16);
    }
    uint32_t sbase = su32(smb);
    int segoff = seg * 8;

    int lrow = lane & 15, lhalf = lane >> 4;
    uint32_t aLane = (uint32_t)(((wm * 64 + lrow) * BSTR + lhalf * 8) * 2);
    uint32_t bLane = (uint32_t)(((wn * 32 + lrow) * BSTR + lhalf * 8) * 2);

    float acc[4][4][4];
    #pragma unroll
    for (int mt = 0; mt < 4; mt++)
        #pragma unroll
        for (int nt = 0; nt < 4; nt++)
            #pragma unroll
            for (int i = 0; i < 4; i++) acc[mt][nt][i] = 0.f;

    // prologue: chunks 0,1 into stages 0,1
    #pragma unroll
    for (int pc = 0; pc < 2; pc++) {
        uint32_t base = sbase + pc * BUFB;
        int k0 = pc * TCK + segoff;
        #pragma unroll
        for (int i = 0; i < 2; i++) {
            CP16(base + 0 * TILEB + doff[i], A + (size_t)arow[i] * DD + k0);
            CP16(base + 1 * TILEB + doff[i], B + (size_t)brow[i] * DD + k0);
        }
        CP_COMMIT();
    }

    int stage = 0, pstage = 2;
    for (int c = 0; c < NCH; c++) {
        if (c == NCH - 1) CP_WAIT0(); else CP_WAIT1();
        __syncthreads();
        if (c + 2 < NCH) {
            uint32_t base = sbase + pstage * BUFB;
            int k0 = (c + 2) * TCK + segoff;
            #pragma unroll
            for (int i = 0; i < 2; i++) {
                CP16(base + 0 * TILEB + doff[i], A + (size_t)arow[i] * DD + k0);
                CP16(base + 1 * TILEB + doff[i], B + (size_t)brow[i] * DD + k0);
            }
            CP_COMMIT();
            pstage++; if (pstage >= NSTAGE) pstage = 0;
        }

        uint32_t sbuf = sbase + stage * BUFB;
        #pragma unroll
        for (int kk = 0; kk < 2; kk++) {
            uint32_t kof = kk * 16 * 2;
            uint32_t bh[4][2];
            uint32_t bb0 = sbuf + 1 * TILEB + bLane + kof;
            LDSM4(bh[0][0], bh[1][0], bh[0][1], bh[1][1], bb0);
            LDSM4(bh[2][0], bh[3][0], bh[2][1], bh[3][1], bb0 + 16 * BSTR * 2);
            #pragma unroll
            for (int mt = 0; mt < 4; mt++) {
                uint32_t ah[4];
                uint32_t aa = sbuf + aLane + kof + mt * 16 * BSTR * 2;
                LDSM4(ah[0], ah[1], ah[2], ah[3], aa);
                #pragma unroll
                for (int nt = 0; nt < 4; nt++)
                    mma_f16(acc[mt][nt], ah, bh[nt]);
            }
        }
        stage++; if (stage >= NSTAGE) stage = 0;
    }

    #pragma unroll
    for (int mt = 0; mt < 4; mt++) {
        #pragma unroll
        for (int half = 0; half < 2; half++) {
            int lr = wm * 64 + mt * 16 + quad + half * 8;
            int r = row0 + lr;
            #pragma unroll
            for (int nt = 0; nt < 4; nt++) {
                int col = col0 + wn * 32 + nt * 8 + tq * 2;
                float v0 = acc[mt][nt][half * 2 + 0] + bias[col];
                float v1 = acc[mt][nt][half * 2 + 1] + bias[col + 1];
                if (MODE == 1) {
                    if (col < DD) {
                        *(uint32_t*)&g_qh[(size_t)r * DD + col] =
                            packf2(v0 * 0.125f, v1 * 0.125f);
                    } else if (col < DD + KVD) {
                        *(uint32_t*)&g_kh[(size_t)r * KVD + (col - DD)] = packf2(v0, v1);
                    } else {
                        int c2 = col - DD - KVD;       // 0..127
                        int gidx = c2 >> 6, d = c2 & 63;
                        int bb2 = r >> 12, pos = r & (LL - 1);
                        size_t vbase = ((size_t)(bb2 * GG + gidx) * 64 + d) * LL + pos;
                        g_vt[vbase]      = __float2half_rn(v0);
                        g_vt[vbase + LL] = __float2half_rn(v1);
                    }
                } else if (MODE == 2) {
                    size_t o = (size_t)r * ldc + col;
                    float2 rr = *(const float2*)&resid[o];
                    *(float2*)&C[o] = make_float2(v0 + rr.x, v1 + rr.y);
                } else {
                    int t2 = stok[lr];
                    if (t2 >= 0) {
                        int tok = t2 >> 1;
                        float w = swt[lr];
                        atomicAdd(&C[(size_t)tok * ldc + col],     w * v0);
                        atomicAdd(&C[(size_t)tok * ldc + col + 1], w * v1);
                    }
                }
            }
        }
    }
}

// ---------------- tensor-core attention: 512 thr, 16 warps x 16 rows -------
__global__ void __launch_bounds__(512)
attn_kernel(__half* __restrict__ oatt) {
    extern __shared__ __half sma[];
    __half* Qh = sma;                  // 256 x APAD

    int n = blockIdx.x, h = blockIdx.y, b = blockIdx.z;
    int g = h & (GG - 1);
    int base = b * LL + n * 128;
    int tid = threadIdx.x, wid = tid >> 5, lane = tid & 31;
    int quad = lane >> 2, tq = lane & 3;
    int lrow = lane & 15, lhalf = lane >> 4;

    uint32_t qBase = su32(Qh);
    uint32_t kvStage[2];
    kvStage[0] = qBase + (uint32_t)(256 * APAD) * 2;
    kvStage[1] = kvStage[0] + (uint32_t)(128 * APAD) * 2;
    uint32_t vOff = (uint32_t)(64 * APAD) * 2;

    // Q cp.async: 4 segs per thread
    {
        int qrow = tid >> 1, qs = (tid & 1) * 4;
        const __half* qsrc = g_qh + (size_t)(base + qrow) * DD + h * 64 + qs * 8;
        uint32_t qdst = qBase + (uint32_t)(qrow * APAD + qs * 8) * 2;
        #pragma unroll
        for (int s2 = 0; s2 < 4; s2++)
            CP16(qdst + s2 * 16, qsrc + s2 * 8);
        CP_COMMIT();
    }

    // K/V: 1 seg each per thread per tile
    int trow = tid >> 3, tseg = tid & 7;
    const __half* ksrc = g_kh + (size_t)(base + trow) * KVD + g * 64 + tseg * 8;
    const __half* vsrc = g_vt + ((size_t)(b * GG + g) * 64 + trow) * LL + n * 128 + tseg * 8;
    uint32_t kdst = (uint32_t)(trow * APAD + tseg * 8) * 2;

    // prologue tiles 0, 1
    #pragma unroll
    for (int pt = 0; pt < 2; pt++) {
        uint32_t kb = kvStage[pt];
        CP16(kb + kdst,        ksrc + (size_t)pt * 64 * KVD);
        CP16(kb + vOff + kdst, vsrc + pt * 64);
        CP_COMMIT();
    }

    float o[8][4];
    #pragma unroll
    for (int nt = 0; nt < 8; nt++)
        #pragma unroll
        for (int i = 0; i < 4; i++) o[nt][i] = 0.f;
    float denomAcc[2] = {0.f, 0.f};

    for (int kt = 0; kt < 4; kt++) {
        if (kt == 3) CP_WAIT0(); else CP_WAIT1();
        __syncthreads();

        uint32_t kBase = kvStage[kt & 1];
        uint32_t vBase = kBase + vOff;

        // ---- S = Q @ K^T ----
        float s[8][4];
        #pragma unroll
        for (int nt = 0; nt < 8; nt++)
            #pragma unroll
            for (int i = 0; i < 4; i++) s[nt][i] = 0.f;

        #pragma unroll
        for (int ks = 0; ks < 4; ks++) {
            uint32_t kof = (uint32_t)(ks * 16 + lhalf * 8) * 2;
            uint32_t ah[4];
            uint32_t aa = qBase + (uint32_t)((wid * 16 + lrow) * APAD) * 2 + kof;
            LDSM4(ah[0], ah[1], ah[2], ah[3], aa);
            uint32_t bh[8][2];
            #pragma unroll
            for (int p = 0; p < 4; p++) {
                uint32_t bb = kBase + (uint32_t)((p * 16 + lrow) * APAD) * 2 + kof;
                LDSM4(bh[2*p][0], bh[2*p+1][0], bh[2*p][1], bh[2*p+1][1], bb);
            }
            #pragma unroll
            for (int nt = 0; nt < 8; nt++)
                mma_f16(s[nt], ah, bh[nt]);
        }

        // ---- exp, denominators, pack P (fp16) ----
        uint32_t ph[8][2];
        {
            float d0 = 0.f, d1 = 0.f;
            #pragma unroll
            for (int nt = 0; nt < 8; nt++) {
                float p0 = __expf(fminf(s[nt][0], 75.f));
                float p1 = __expf(fminf(s[nt][1], 75.f));
                float p2 = __expf(fminf(s[nt][2], 75.f));
                float p3 = __expf(fminf(s[nt][3], 75.f));
                d0 += p0 + p1;
                d1 += p2 + p3;
                ph[nt][0] = packf2(p0, p1);
                ph[nt][1] = packf2(p2, p3);
            }
            d0 += __shfl_xor_sync(0xffffffffu, d0, 1);
            d0 += __shfl_xor_sync(0xffffffffu, d0, 2);
            d1 += __shfl_xor_sync(0xffffffffu, d1, 1);
            d1 += __shfl_xor_sync(0xffffffffu, d1, 2);
            denomAcc[0] += d0;
            denomAcc[1] += d1;
        }

        // ---- O += P @ V^T ----
        #pragma unroll
        for (int ks = 0; ks < 4; ks++) {
            uint32_t kof = (uint32_t)(ks * 16 + lhalf * 8) * 2;
            uint32_t bvh[8][2];
            #pragma unroll
            for (int p = 0; p < 4; p++) {
                uint32_t bb = vBase + (uint32_t)((p * 16 + lrow) * APAD) * 2 + kof;
                LDSM4(bvh[2*p][0], bvh[2*p+1][0], bvh[2*p][1], bvh[2*p+1][1], bb);
            }
            uint32_t ah4[4] = { ph[2*ks][0], ph[2*ks][1], ph[2*ks+1][0], ph[2*ks+1][1] };
            #pragma unroll
            for (int nt = 0; nt < 8; nt++)
                mma_f16(o[nt], ah4, bvh[nt]);
        }

        // prefetch tile kt+2 into the stage just consumed
        if (kt + 2 < 4) {
            __syncthreads();
            int pt = kt + 2;
            uint32_t kb = kvStage[kt & 1];
            CP16(kb + kdst,        ksrc + (size_t)pt * 64 * KVD);
            CP16(kb + vOff + kdst, vsrc + pt * 64);
            CP_COMMIT();
        }
    }

    // ---- epilogue ----
    #pragma unroll
    for (int half = 0; half < 2; half++) {
        float inv = 1.f / denomAcc[half];
        int tokout = b * LL + n * 256 + wid * 16 + quad + half * 8;
        size_t rowb = (size_t)tokout * DD + h * 64;
        #pragma unroll
        for (int nt = 0; nt < 8; nt++) {
            float v0 = o[nt][half * 2 + 0] * inv;
            float v1 = o[nt][half * 2 + 1] * inv;
            int col = nt * 8 + tq * 2;
            *(uint32_t*)&oatt[rowb + col] = packf2(v0, v1);
        }
    }
}

// ---------------- aux scalar ----------------
__global__ void aux_kernel(float* __restrict__ out, long long out_size) {
    if (threadIdx.x == 0 && blockIdx.x == 0) {
        float pen = 0.f;
        #pragma unroll
        for (int e = 0; e < EE; e++) {
            float usage = (float)g_ecount[e] / ((float)NTOK + 1e-8f);
            pen += fmaxf(usage - 0.4f, 0.f);
        }
        float ent = g_entsum / (float)NTOK;
        float aux = 0.05f * ent + pen;
        long long total = (long long)NTOK * HID;
        if (out_size > total) out[total] = aux;
    }
}

// ---------------- launch ----------------
extern "C" void kernel_launch(void* const* d_in, const int* in_sizes, int n_in,
                              void* d_out, int out_size) {
    const float* x     = (const float*)d_in[0];
    const float* Wq    = (const float*)d_in[1];
    const float* bq    = (const float*)d_in[2];
    const float* Wk    = (const float*)d_in[3];
    const float* bk    = (const float*)d_in[4];
    const float* Wv    = (const float*)d_in[5];
    const float* bv    = (const float*)d_in[6];
    const float* Wo    = (const float*)d_in[7];
    const float* bo    = (const float*)d_in[8];
    const float* ln1_g = (const float*)d_in[9];
    const float* ln1_b = (const float*)d_in[10];
    const float* ln2_g = (const float*)d_in[11];
    const float* ln2_b = (const float*)d_in[12];
    const float* Wg    = (const float*)d_in[13];
    const float* bg    = (const float*)d_in[14];
    const float* We    = (const float*)d_in[15];
    const float* be    = (const float*)d_in[16];
    float* out = (float*)d_out;

    __half *ln1, *att, *ln2, *wqkv, *wot, *wet;
    float *bqkv;
    cudaGetSymbolAddress((void**)&ln1,  g_ln1);
    cudaGetSymbolAddress((void**)&att,  g_att);
    cudaGetSymbolAddress((void**)&ln2,  g_ln2);
    cudaGetSymbolAddress((void**)&wqkv, g_wqkv);
    cudaGetSymbolAddress((void**)&wot,  g_wot);
    cudaGetSymbolAddress((void**)&wet,  g_wet);
    cudaGetSymbolAddress((void**)&bqkv, g_bqkv);

    const int ASM = (256 + 2 * 128) * APAD * 2;   // 73728
    cudaFuncSetAttribute(attn_kernel, cudaFuncAttributeMaxDynamicSharedMemorySize, ASM);
    cudaFuncSetAttribute(tc_gemm<1>, cudaFuncAttributeMaxDynamicSharedMemorySize, GSMEM);
    cudaFuncSetAttribute(tc_gemm<2>, cudaFuncAttributeMaxDynamicSharedMemorySize, GSMEM);
    cudaFuncSetAttribute(tc_gemm<3>, cudaFuncAttributeMaxDynamicSharedMemorySize, GSMEM);

    // side stream for the Wo/We weight prep (graph-capturable fork/join)
    cudaStream_t s2;
    cudaEvent_t evFork, evJoin;
    cudaStreamCreateWithFlags(&s2, cudaStreamNonBlocking);
    cudaEventCreateWithFlags(&evFork, cudaEventDisableTiming);
    cudaEventCreateWithFlags(&evJoin, cudaEventDisableTiming);

    transpose_qkv<<<1285, dim3(32, 8)>>>(Wq, Wk, Wv, bq, bk, bv);

    cudaEventRecord(evFork, 0);
    cudaStreamWaitEvent(s2, evFork, 0);
    transpose_owe<<<9216, dim3(32, 8), 0, s2>>>(Wo, We);
    cudaEventRecord(evJoin, s2);

    ln_kernel<<<NTOK, 256>>>(x, ln1_g, ln1_b, ln1);

    tc_gemm<1><<<dim3(10, 64), 256, GSMEM>>>(ln1, wqkv, bqkv, nullptr, nullptr, 0);

    attn_kernel<<<dim3(NWIN, HH, BB), 512, ASM>>>(att);

    cudaStreamWaitEvent(0, evJoin, 0);

    tc_gemm<2><<<dim3(8, 64), 256, GSMEM>>>(att, wot, bo, x, out, DD);

    ln2_gate_kernel<<<NTOK, 256>>>(out, ln2_g, ln2_b, Wg, bg, ln2);

    tc_gemm<3><<<dim3(8, 64, EE), 256, GSMEM>>>(ln2, wet, be, nullptr, out, HID);

    aux_kernel<<<1, 32>>>(out, (long long)out_size);
}